// round 6
// baseline (speedup 1.0000x reference)
#include <cuda_runtime.h>

// QSP expectation, single fused kernel, zero inter-block communication.
//
// g(theta) = Re( e^{i phi0} P00(theta) ) = sum_{j=0..27} A_j cos(2j theta) + B_j sin(2j theta)
// Every block redundantly samples the 54-step chain at theta_k = pi k/64 and
// extracts A_j,B_j by exact table-based 64-point DFT, then evaluates the series
// with two f32x2-packed Clenshaw pairs (4 elements/thread).
// (A,B) packed as one LDS.128 with 3-deep software prefetch (fixed: pipeline
// now reaches sAB[0]), 256-thread blocks x 512 (4 blocks/SM), eval-path LDGs
// issued before precompute.

#define NSTEP 54
#define NHARM 27
#define NSAMP 64

typedef unsigned long long u64;

__device__ __forceinline__ u64 pk2(float lo, float hi) {
    u64 r; asm("mov.b64 %0, {%1, %2};" : "=l"(r) : "f"(lo), "f"(hi)); return r;
}
__device__ __forceinline__ void upk2(u64 v, float& lo, float& hi) {
    asm("mov.b64 {%0, %1}, %2;" : "=f"(lo), "=f"(hi) : "l"(v));
}
__device__ __forceinline__ u64 fma2(u64 a, u64 b, u64 c) {
    u64 d; asm("fma.rn.f32x2 %0, %1, %2, %3;" : "=l"(d) : "l"(a), "l"(b), "l"(c)); return d;
}
__device__ __forceinline__ u64 sub2(u64 a, u64 b) {
    u64 d; asm("sub.rn.f32x2 %0, %1, %2;" : "=l"(d) : "l"(a), "l"(b)); return d;
}

__global__ void __launch_bounds__(256, 4)
qsp_fused(const float4* __restrict__ x4,
          const float*  __restrict__ phis,
          const float4* __restrict__ a4,
          const float*  __restrict__ bias,
          float4* __restrict__ out4,
          int nq)                       // nq = n/4
{
    __shared__ float pc[NSTEP], ps[NSTEP];
    __shared__ float gs[NSAMP];
    __shared__ float tab[NSAMP];
    __shared__ float s0cs[2];
    __shared__ __align__(16) ulonglong2 sAB[NHARM + 1];   // .x = A_k packed, .y = B_k packed

    const int t = threadIdx.x;
    const int T = blockIdx.x * blockDim.x + t;
    const bool act = (T < nq);

    // ---- issue eval-path global loads EARLY (latency hidden by precompute) ----
    float4 xv = make_float4(0.f, 0.f, 0.f, 0.f);
    float4 av = xv;
    if (act) { xv = x4[T]; av = a4[T]; }
    const float bb = bias[0];

    // ---- per-block coefficient precompute (redundant, cheap) ----
    if (t < NSTEP) {
        float sp, cp; sincosf(phis[t + 1], &sp, &cp);   // accurate (error-critical, one-time)
        pc[t] = cp; ps[t] = sp;
    }
    if (t == 63) {
        float sp, cp; sincosf(phis[0], &sp, &cp);
        s0cs[0] = cp; s0cs[1] = sp;
    }
    if (t >= 64 && t < 64 + NSAMP) {
        const int i = t - 64;
        tab[i] = sinpif((float)i * (1.0f / 32.0f));     // sin(pi*i/32), period 64
    }
    __syncthreads();

    if (t < NSAMP) {
        // chain at theta = pi*t/64 (row 0 of the unitary product only)
        float s, c; sincospif((float)t * (1.0f / 64.0f), &s, &c);
        float x0 = 1.0f, y0 = 0.0f, x1 = 0.0f, y1 = 0.0f;
        #pragma unroll
        for (int k = 0; k < NSTEP; ++k) {
            const float ec = pc[k], es = ps[k];
            const float ux = c * x0 - s * y1;
            const float uy = c * y0 + s * x1;
            const float vx = c * x1 - s * y0;
            const float vy = c * y1 + s * x0;
            x0 = ec * ux - es * uy;
            y0 = es * ux + ec * uy;
            x1 = ec * vx + es * vy;
            y1 = ec * vy - es * vx;
        }
        gs[t] = s0cs[0] * x0 - s0cs[1] * y0;
    }
    __syncthreads();

    // exact 64-point DFT via table: cos(pi*m/32) = tab[(m+16)&63]
    if (t <= NHARM) {
        float a0 = 0.f, a1 = 0.f, a2s = 0.f, a3 = 0.f;
        #pragma unroll
        for (int k = 0; k < NSAMP; k += 4) {
            a0  = fmaf(gs[k+0], tab[(t*(k+0) + 16) & 63], a0);
            a1  = fmaf(gs[k+1], tab[(t*(k+1) + 16) & 63], a1);
            a2s = fmaf(gs[k+2], tab[(t*(k+2) + 16) & 63], a2s);
            a3  = fmaf(gs[k+3], tab[(t*(k+3) + 16) & 63], a3);
        }
        const float v = ((a0 + a1) + (a2s + a3)) *
                        ((t == 0) ? (1.0f / 64.0f) : (2.0f / 64.0f));
        sAB[t].x = pk2(v, v);
        if (t == 0) sAB[0].y = 0ull;   // B_0 unused
    } else if (t >= 32 && t <= 31 + NHARM) {
        const int j = t - 31;   // 1..27
        float a0 = 0.f, a1 = 0.f, a2s = 0.f, a3 = 0.f;
        #pragma unroll
        for (int k = 0; k < NSAMP; k += 4) {
            a0  = fmaf(gs[k+0], tab[(j*(k+0)) & 63], a0);
            a1  = fmaf(gs[k+1], tab[(j*(k+1)) & 63], a1);
            a2s = fmaf(gs[k+2], tab[(j*(k+2)) & 63], a2s);
            a3  = fmaf(gs[k+3], tab[(j*(k+3)) & 63], a3);
        }
        const float v = ((a0 + a1) + (a2s + a3)) * (2.0f / 64.0f);
        sAB[j].y = pk2(v, v);
    }
    __syncthreads();

    // ---- evaluation: 4 elements/thread, two packed Clenshaw pairs ----
    if (!act) return;

    float s0, c0, s1, c1, s2, c2, s3, c3;
    __sincosf(2.0f * xv.x, &s0, &c0);
    __sincosf(2.0f * xv.y, &s1, &c1);
    __sincosf(2.0f * xv.z, &s2, &c2);
    __sincosf(2.0f * xv.w, &s3, &c3);

    const u64 twA = pk2(2.0f * c0, 2.0f * c1);
    const u64 twB = pk2(2.0f * c2, 2.0f * c3);
    const u64 cuA = pk2(c0, c1), suA = pk2(s0, s1);
    const u64 cuB = pk2(c2, c3), suB = pk2(s2, s3);

    u64 b1A = 0, b2A = 0, d1A = 0, d2A = 0;
    u64 b1B = 0, b2B = 0, d1B = 0, d2B = 0;

    // 3-deep rolling prefetch of packed (A_k,B_k): LDS.128 issued 3 iters ahead.
    // Pipeline invariant: at iteration k, f0 == sAB[k]; loads run sAB[24]..sAB[0]
    // (guard k >= 3 so sAB[0] IS loaded; after the loop f0 == sAB[0]).
    ulonglong2 f0 = sAB[NHARM];
    ulonglong2 f1 = sAB[NHARM - 1];
    ulonglong2 f2 = sAB[NHARM - 2];

    #pragma unroll
    for (int k = NHARM; k >= 1; --k) {
        const u64 Ak = f0.x, Bk = f0.y;
        f0 = f1; f1 = f2;
        if (k >= 3) f2 = sAB[k - 3];

        u64 nb;
        nb = fma2(twA, b1A, sub2(Ak, b2A)); b2A = b1A; b1A = nb;
        nb = fma2(twA, d1A, sub2(Bk, d2A)); d2A = d1A; d1A = nb;
        nb = fma2(twB, b1B, sub2(Ak, b2B)); b2B = b1B; b1B = nb;
        nb = fma2(twB, d1B, sub2(Bk, d2B)); d2B = d1B; d1B = nb;
    }

    const u64 A0 = f0.x;          // == sAB[0].x via the pipeline
    u64 fA = sub2(A0, b2A);
    fA = fma2(cuA, b1A, fA);
    fA = fma2(suA, d1A, fA);
    u64 fB = sub2(A0, b2B);
    fB = fma2(cuB, b1B, fB);
    fB = fma2(suB, d1B, fB);

    float g0, g1, g2, g3;
    upk2(fA, g0, g1);
    upk2(fB, g2, g3);

    out4[T] = make_float4(fmaf(av.x, g0, bb), fmaf(av.y, g1, bb),
                          fmaf(av.z, g2, bb), fmaf(av.w, g3, bb));
}

// ---------------------------------------------------------------------------
// Fallback for unexpected shapes (direct chain evaluation).
// ---------------------------------------------------------------------------
__global__ void __launch_bounds__(256)
qsp_generic(const float* __restrict__ x,
            const float* __restrict__ phis,
            const float* __restrict__ alphas,
            const float* __restrict__ bias,
            float* __restrict__ out,
            int n, int nsteps)
{
    __shared__ float pc[256], ps[256];
    __shared__ float s0c, s0s;
    int t = threadIdx.x;
    if (t < nsteps && t < 256) {
        float sp, cp; sincosf(phis[t + 1], &sp, &cp);
        pc[t] = cp; ps[t] = sp;
    }
    if (t == 0) {
        float sp, cp; sincosf(phis[0], &sp, &cp);
        s0c = cp; s0s = sp;
    }
    __syncthreads();

    const int i = blockIdx.x * blockDim.x + t;
    if (i >= n) return;

    float s, c; sincosf(x[i], &s, &c);
    float x0 = 1.0f, y0 = 0.0f, x1 = 0.0f, y1 = 0.0f;
    for (int k = 0; k < nsteps; ++k) {
        const float ec = (k < 256) ? pc[k] : cosf(phis[k + 1]);
        const float es = (k < 256) ? ps[k] : sinf(phis[k + 1]);
        const float ux = c * x0 - s * y1;
        const float uy = c * y0 + s * x1;
        const float vx = c * x1 - s * y0;
        const float vy = c * y1 + s * x0;
        x0 = ec * ux - es * uy;
        y0 = es * ux + ec * uy;
        x1 = ec * vx + es * vy;
        y1 = ec * vy - es * vx;
    }
    const float re = s0c * x0 - s0s * y0;
    out[i] = fmaf(alphas[i], re, bias[0]);
}

extern "C" void kernel_launch(void* const* d_in, const int* in_sizes, int n_in,
                              void* d_out, int out_size)
{
    const float* x      = (const float*)d_in[0];
    const float* phis   = (const float*)d_in[1];
    const float* alphas = (const float*)d_in[2];
    const float* bias   = (const float*)d_in[3];
    float* out = (float*)d_out;

    const int n      = in_sizes[0];
    const int nph    = in_sizes[1];
    const int nsteps = nph - 1;

    if (nsteps == NSTEP && (n & 3) == 0) {
        const int nq      = n >> 2;                  // float4 quads
        const int threads = 256;
        const int blocks  = (nq + threads - 1) / threads;   // 512 for n=524288
        qsp_fused<<<blocks, threads>>>((const float4*)x, phis,
                                       (const float4*)alphas, bias,
                                       (float4*)out, nq);
    } else {
        const int threads = 256;
        const int blocks  = (n + threads - 1) / threads;
        qsp_generic<<<blocks, threads>>>(x, phis, alphas, bias, out, n, nsteps);
    }
}

// round 7
// speedup vs baseline: 1.3801x; 1.3801x over previous
#include <cuda_runtime.h>

// QSP expectation, single fused kernel, zero inter-block communication.
//
// g(theta) = Re( e^{i phi0} P00(theta) ) = sum_{j=0..27} A_j cos(2j theta) + B_j sin(2j theta)
// Each block (one per SM) redundantly samples the 54-step chain at
// theta_k = pi k/64, extracts A_j,B_j via an exact table-based 64-point DFT,
// then 1024 threads evaluate the series with two f32x2-packed Clenshaw pairs
// (4 elements/thread). (A_k,B_k) packed as one LDS.128 with a 2-deep rolling
// prefetch; eval sincos/packing hoisted BEFORE the coefficient barrier so the
// 30 non-chain warps work during precompute.

#define NSTEP 54
#define NHARM 27
#define NSAMP 64

typedef unsigned long long u64;

__device__ __forceinline__ u64 pk2(float lo, float hi) {
    u64 r; asm("mov.b64 %0, {%1, %2};" : "=l"(r) : "f"(lo), "f"(hi)); return r;
}
__device__ __forceinline__ void upk2(u64 v, float& lo, float& hi) {
    asm("mov.b64 {%0, %1}, %2;" : "=f"(lo), "=f"(hi) : "l"(v));
}
__device__ __forceinline__ u64 fma2(u64 a, u64 b, u64 c) {
    u64 d; asm("fma.rn.f32x2 %0, %1, %2, %3;" : "=l"(d) : "l"(a), "l"(b), "l"(c)); return d;
}
__device__ __forceinline__ u64 sub2(u64 a, u64 b) {
    u64 d; asm("sub.rn.f32x2 %0, %1, %2;" : "=l"(d) : "l"(a), "l"(b)); return d;
}

__global__ void __launch_bounds__(1024, 1)
qsp_fused(const float4* __restrict__ x4,
          const float*  __restrict__ phis,
          const float4* __restrict__ a4,
          const float*  __restrict__ bias,
          float4* __restrict__ out4,
          int nq)                       // nq = n/4
{
    __shared__ float pc[NSTEP], ps[NSTEP];
    __shared__ float gs[NSAMP];
    __shared__ float tab[NSAMP];
    __shared__ float s0cs[2];
    __shared__ __align__(16) ulonglong2 sAB[NHARM + 1];   // .x = A_k packed, .y = B_k packed

    const int t = threadIdx.x;
    const int T = blockIdx.x * blockDim.x + t;
    const bool act = (T < nq);

    // ---- eval-path global loads issued FIRST (latency hidden by precompute) ----
    float4 xv = make_float4(0.f, 0.f, 0.f, 0.f);
    float4 av = xv;
    if (act) { xv = x4[T]; av = a4[T]; }
    const float bb = bias[0];

    // ---- per-block coefficient precompute setup ----
    if (t < NSTEP) {
        float sp, cp; sincosf(phis[t + 1], &sp, &cp);   // accurate (error-critical, one-time)
        pc[t] = cp; ps[t] = sp;
    }
    if (t == 63) {
        float sp, cp; sincosf(phis[0], &sp, &cp);
        s0cs[0] = cp; s0cs[1] = sp;
    }
    if (t >= 64 && t < 64 + NSAMP) {
        const int i = t - 64;
        tab[i] = sinpif((float)i * (1.0f / 32.0f));     // sin(pi*i/32), period 64
    }

    // ---- eval sincos + packing: independent of coefficients, done pre-barrier ----
    float s0, c0, s1, c1, s2, c2, s3, c3;
    __sincosf(2.0f * xv.x, &s0, &c0);
    __sincosf(2.0f * xv.y, &s1, &c1);
    __sincosf(2.0f * xv.z, &s2, &c2);
    __sincosf(2.0f * xv.w, &s3, &c3);
    const u64 twA = pk2(2.0f * c0, 2.0f * c1);
    const u64 twB = pk2(2.0f * c2, 2.0f * c3);
    const u64 cuA = pk2(c0, c1), suA = pk2(s0, s1);
    const u64 cuB = pk2(c2, c3), suB = pk2(s2, s3);

    __syncthreads();

    if (t < NSAMP) {
        // chain at theta = pi*t/64 (row 0 of the unitary product only)
        float s, c; sincospif((float)t * (1.0f / 64.0f), &s, &c);
        float x0 = 1.0f, y0 = 0.0f, x1 = 0.0f, y1 = 0.0f;
        #pragma unroll
        for (int k = 0; k < NSTEP; ++k) {
            const float ec = pc[k], es = ps[k];
            const float ux = c * x0 - s * y1;
            const float uy = c * y0 + s * x1;
            const float vx = c * x1 - s * y0;
            const float vy = c * y1 + s * x0;
            x0 = ec * ux - es * uy;
            y0 = es * ux + ec * uy;
            x1 = ec * vx + es * vy;
            y1 = ec * vy - es * vx;
        }
        gs[t] = s0cs[0] * x0 - s0cs[1] * y0;
    }
    __syncthreads();

    // exact 64-point DFT via table: cos(pi*m/32) = tab[(m+16)&63]
    if (t <= NHARM) {
        float a0 = 0.f, a1 = 0.f, a2s = 0.f, a3 = 0.f;
        #pragma unroll
        for (int k = 0; k < NSAMP; k += 4) {
            a0  = fmaf(gs[k+0], tab[(t*(k+0) + 16) & 63], a0);
            a1  = fmaf(gs[k+1], tab[(t*(k+1) + 16) & 63], a1);
            a2s = fmaf(gs[k+2], tab[(t*(k+2) + 16) & 63], a2s);
            a3  = fmaf(gs[k+3], tab[(t*(k+3) + 16) & 63], a3);
        }
        const float v = ((a0 + a1) + (a2s + a3)) *
                        ((t == 0) ? (1.0f / 64.0f) : (2.0f / 64.0f));
        sAB[t].x = pk2(v, v);
        if (t == 0) sAB[0].y = 0ull;   // B_0 unused
    } else if (t >= 32 && t <= 31 + NHARM) {
        const int j = t - 31;   // 1..27
        float a0 = 0.f, a1 = 0.f, a2s = 0.f, a3 = 0.f;
        #pragma unroll
        for (int k = 0; k < NSAMP; k += 4) {
            a0  = fmaf(gs[k+0], tab[(j*(k+0)) & 63], a0);
            a1  = fmaf(gs[k+1], tab[(j*(k+1)) & 63], a1);
            a2s = fmaf(gs[k+2], tab[(j*(k+2)) & 63], a2s);
            a3  = fmaf(gs[k+3], tab[(j*(k+3)) & 63], a3);
        }
        const float v = ((a0 + a1) + (a2s + a3)) * (2.0f / 64.0f);
        sAB[j].y = pk2(v, v);
    }
    __syncthreads();

    // ---- evaluation: 4 elements/thread, two packed Clenshaw pairs ----
    if (!act) return;

    u64 b1A = 0, b2A = 0, d1A = 0, d2A = 0;
    u64 b1B = 0, b2B = 0, d1B = 0, d2B = 0;

    // 2-deep rolling prefetch of packed (A_k,B_k) via LDS.128.
    // Invariant: at iteration k, f0 == sAB[k]; loads run sAB[25]..sAB[0]
    // (guard k >= 2), so after the loop f0 == sAB[0].
    ulonglong2 f0 = sAB[NHARM];
    ulonglong2 f1 = sAB[NHARM - 1];

    #pragma unroll
    for (int k = NHARM; k >= 1; --k) {
        const u64 Ak = f0.x, Bk = f0.y;
        f0 = f1;
        if (k >= 2) f1 = sAB[k - 2];

        u64 nb;
        nb = fma2(twA, b1A, sub2(Ak, b2A)); b2A = b1A; b1A = nb;
        nb = fma2(twA, d1A, sub2(Bk, d2A)); d2A = d1A; d1A = nb;
        nb = fma2(twB, b1B, sub2(Ak, b2B)); b2B = b1B; b1B = nb;
        nb = fma2(twB, d1B, sub2(Bk, d2B)); d2B = d1B; d1B = nb;
    }

    const u64 A0 = f0.x;          // == sAB[0].x via the pipeline
    u64 fA = sub2(A0, b2A);
    fA = fma2(cuA, b1A, fA);
    fA = fma2(suA, d1A, fA);
    u64 fB = sub2(A0, b2B);
    fB = fma2(cuB, b1B, fB);
    fB = fma2(suB, d1B, fB);

    float g0, g1, g2, g3;
    upk2(fA, g0, g1);
    upk2(fB, g2, g3);

    out4[T] = make_float4(fmaf(av.x, g0, bb), fmaf(av.y, g1, bb),
                          fmaf(av.z, g2, bb), fmaf(av.w, g3, bb));
}

// ---------------------------------------------------------------------------
// Fallback for unexpected shapes (direct chain evaluation).
// ---------------------------------------------------------------------------
__global__ void __launch_bounds__(256)
qsp_generic(const float* __restrict__ x,
            const float* __restrict__ phis,
            const float* __restrict__ alphas,
            const float* __restrict__ bias,
            float* __restrict__ out,
            int n, int nsteps)
{
    __shared__ float pc[256], ps[256];
    __shared__ float s0c, s0s;
    int t = threadIdx.x;
    if (t < nsteps && t < 256) {
        float sp, cp; sincosf(phis[t + 1], &sp, &cp);
        pc[t] = cp; ps[t] = sp;
    }
    if (t == 0) {
        float sp, cp; sincosf(phis[0], &sp, &cp);
        s0c = cp; s0s = sp;
    }
    __syncthreads();

    const int i = blockIdx.x * blockDim.x + t;
    if (i >= n) return;

    float s, c; sincosf(x[i], &s, &c);
    float x0 = 1.0f, y0 = 0.0f, x1 = 0.0f, y1 = 0.0f;
    for (int k = 0; k < nsteps; ++k) {
        const float ec = (k < 256) ? pc[k] : cosf(phis[k + 1]);
        const float es = (k < 256) ? ps[k] : sinf(phis[k + 1]);
        const float ux = c * x0 - s * y1;
        const float uy = c * y0 + s * x1;
        const float vx = c * x1 - s * y0;
        const float vy = c * y1 + s * x0;
        x0 = ec * ux - es * uy;
        y0 = es * ux + ec * uy;
        x1 = ec * vx + es * vy;
        y1 = ec * vy - es * vx;
    }
    const float re = s0c * x0 - s0s * y0;
    out[i] = fmaf(alphas[i], re, bias[0]);
}

extern "C" void kernel_launch(void* const* d_in, const int* in_sizes, int n_in,
                              void* d_out, int out_size)
{
    const float* x      = (const float*)d_in[0];
    const float* phis   = (const float*)d_in[1];
    const float* alphas = (const float*)d_in[2];
    const float* bias   = (const float*)d_in[3];
    float* out = (float*)d_out;

    const int n      = in_sizes[0];
    const int nph    = in_sizes[1];
    const int nsteps = nph - 1;

    if (nsteps == NSTEP && (n & 3) == 0) {
        const int nq      = n >> 2;                   // float4 quads
        const int threads = 1024;
        const int blocks  = (nq + threads - 1) / threads;   // 128 for n=524288
        qsp_fused<<<blocks, threads>>>((const float4*)x, phis,
                                       (const float4*)alphas, bias,
                                       (float4*)out, nq);
    } else {
        const int threads = 256;
        const int blocks  = (n + threads - 1) / threads;
        qsp_generic<<<blocks, threads>>>(x, phis, alphas, bias, out, n, nsteps);
    }
}

// round 8
// speedup vs baseline: 1.7226x; 1.2482x over previous
#include <cuda_runtime.h>

// QSP expectation via per-block table + cubic interpolation.
//
// g(theta) = Re(e^{i phi0} P00) = sum_{j<=27} A_j cos(2j th) + B_j sin(2j th)
//   -> pi-periodic, band-limited (54). Per block (one per SM):
//   1) 54-step chain split into two 27-step halves (rows x cols, 128 threads)
//      at 64 samples -> exact 64-pt DFT -> A_j, B_j.
//   2) every thread evaluates the series at 2 grid points (packed Clenshaw)
//      -> 2048-entry table of g over [0, pi), plus a float4 stencil table.
//   3) eval: range-reduce theta, one LDS.128, cubic Lagrange, fma out.

#define NSTEP 54
#define NHARM 27
#define NSAMP 64
#define TSIZE 2048

typedef unsigned long long u64;

__device__ __forceinline__ u64 pk2(float lo, float hi) {
    u64 r; asm("mov.b64 %0, {%1, %2};" : "=l"(r) : "f"(lo), "f"(hi)); return r;
}
__device__ __forceinline__ void upk2(u64 v, float& lo, float& hi) {
    asm("mov.b64 {%0, %1}, %2;" : "=f"(lo), "=f"(hi) : "l"(v));
}
__device__ __forceinline__ u64 fma2(u64 a, u64 b, u64 c) {
    u64 d; asm("fma.rn.f32x2 %0, %1, %2, %3;" : "=l"(d) : "l"(a), "l"(b), "l"(c)); return d;
}
__device__ __forceinline__ u64 sub2(u64 a, u64 b) {
    u64 d; asm("sub.rn.f32x2 %0, %1, %2;" : "=l"(d) : "l"(a), "l"(b)); return d;
}

__global__ void __launch_bounds__(1024, 1)
qsp_fused(const float4* __restrict__ x4,
          const float*  __restrict__ phis,
          const float4* __restrict__ a4,
          const float*  __restrict__ bias,
          float4* __restrict__ out4,
          int nq)                       // nq = n/4
{
    __shared__ float pc[NSTEP], ps[NSTEP];
    __shared__ float s0cs[2];
    __shared__ float lh[64 * 4], rh[64 * 4];      // half-chain results
    __shared__ float gs[NSAMP];                   // g at 64 chain samples
    __shared__ float tab[NSAMP];                  // sinpi table for DFT
    __shared__ __align__(16) ulonglong2 sAB[NHARM + 1];
    __shared__ __align__(16) float g[TSIZE];      // g over one period
    __shared__ __align__(16) float4 t4[TSIZE];    // stencil g[i-1..i+2]

    const int t = threadIdx.x;
    const int T = blockIdx.x * blockDim.x + t;
    const bool act = (T < nq);

    // ---- eval-path global loads issued FIRST ----
    float4 xv = make_float4(0.f, 0.f, 0.f, 0.f);
    float4 av = xv;
    if (act) { xv = x4[T]; av = a4[T]; }
    const float bb = bias[0];

    // ---- phase setup ----
    if (t < NSTEP) {
        float sp, cp; sincosf(phis[t + 1], &sp, &cp);   // accurate, one-time
        pc[t] = cp; ps[t] = sp;
    }
    if (t == 192) {
        float sp, cp; sincosf(phis[0], &sp, &cp);
        s0cs[0] = cp; s0cs[1] = sp;
    }
    if (t >= 128 && t < 128 + NSAMP) {
        const int i = t - 128;
        tab[i] = sinpif((float)i * (1.0f / 32.0f));     // sin(pi*i/32)
    }
    __syncthreads();

    // ---- chain split: threads 0-63 left rows, 64-127 right (transposed) ----
    if (t < 128) {
        const int i = t & 63;
        float s, c; sincospif((float)i * (1.0f / 64.0f), &s, &c);
        float x0, y0, x1, y1;
        if (t < 64) {
            // row r = e0^T * M_1..M_27, iterate r <- r*(W S)
            x0 = 1.f; y0 = 0.f; x1 = 0.f; y1 = 0.f;
            #pragma unroll
            for (int k = 0; k < NHARM; ++k) {
                const float ec = pc[k], es = ps[k];
                const float ux = c * x0 - s * y1, uy = c * y0 + s * x1;
                const float vx = c * x1 - s * y0, vy = c * y1 + s * x0;
                x0 = ec * ux - es * uy; y0 = es * ux + ec * uy;
                x1 = ec * vx + es * vy; y1 = ec * vy - es * vx;
            }
            lh[i*4+0] = x0; lh[i*4+1] = y0; lh[i*4+2] = x1; lh[i*4+3] = y1;
        } else {
            // col v = M_28..M_54 * e0 via transpose rows: r <- r*(S_k W), k=53..27
            x0 = 1.f; y0 = 0.f; x1 = 0.f; y1 = 0.f;
            #pragma unroll
            for (int k = NSTEP - 1; k >= NHARM; --k) {
                const float ec = pc[k], es = ps[k];
                const float px = ec * x0 - es * y0, py = ec * y0 + es * x0;
                const float qx = ec * x1 + es * y1, qy = ec * y1 - es * x1;
                x0 = c * px - s * qy;  y0 = c * py + s * qx;
                x1 = c * qx - s * py;  y1 = c * qy + s * px;
            }
            rh[i*4+0] = x0; rh[i*4+1] = y0; rh[i*4+2] = x1; rh[i*4+3] = y1;
        }
    }
    __syncthreads();

    if (t < 64) {
        // P00 = r0*v0 + r1*v1 (complex), then Re(e^{i phi0} * P00)
        const float r0x = lh[t*4], r0y = lh[t*4+1], r1x = lh[t*4+2], r1y = lh[t*4+3];
        const float v0x = rh[t*4], v0y = rh[t*4+1], v1x = rh[t*4+2], v1y = rh[t*4+3];
        const float Px = r0x*v0x - r0y*v0y + r1x*v1x - r1y*v1y;
        const float Py = r0x*v0y + r0y*v0x + r1x*v1y + r1y*v1x;
        gs[t] = s0cs[0] * Px - s0cs[1] * Py;
    }
    __syncthreads();

    // ---- exact 64-pt DFT: cos(pi*m/32) = tab[(m+16)&63] ----
    if (t <= NHARM) {
        float a0 = 0.f, a1 = 0.f, a2s = 0.f, a3 = 0.f;
        #pragma unroll
        for (int k = 0; k < NSAMP; k += 4) {
            a0  = fmaf(gs[k+0], tab[(t*(k+0) + 16) & 63], a0);
            a1  = fmaf(gs[k+1], tab[(t*(k+1) + 16) & 63], a1);
            a2s = fmaf(gs[k+2], tab[(t*(k+2) + 16) & 63], a2s);
            a3  = fmaf(gs[k+3], tab[(t*(k+3) + 16) & 63], a3);
        }
        const float v = ((a0 + a1) + (a2s + a3)) *
                        ((t == 0) ? (1.0f / 64.0f) : (2.0f / 64.0f));
        sAB[t].x = pk2(v, v);
        if (t == 0) sAB[0].y = 0ull;
    } else if (t >= 32 && t <= 31 + NHARM) {
        const int j = t - 31;
        float a0 = 0.f, a1 = 0.f, a2s = 0.f, a3 = 0.f;
        #pragma unroll
        for (int k = 0; k < NSAMP; k += 4) {
            a0  = fmaf(gs[k+0], tab[(j*(k+0)) & 63], a0);
            a1  = fmaf(gs[k+1], tab[(j*(k+1)) & 63], a1);
            a2s = fmaf(gs[k+2], tab[(j*(k+2)) & 63], a2s);
            a3  = fmaf(gs[k+3], tab[(j*(k+3)) & 63], a3);
        }
        const float v = ((a0 + a1) + (a2s + a3)) * (2.0f / 64.0f);
        sAB[j].y = pk2(v, v);
    }
    __syncthreads();

    // ---- table build: each thread evaluates g at grid points 2t, 2t+1 ----
    {
        // 2*theta_m = pi*m/1024 for m = 2t, 2t+1
        float sa, ca, sb, cb;
        sincospif((float)(2*t)     * (1.0f / 1024.0f), &sa, &ca);
        sincospif((float)(2*t + 1) * (1.0f / 1024.0f), &sb, &cb);
        const u64 tw = pk2(2.0f * ca, 2.0f * cb);
        const u64 cu = pk2(ca, cb), su = pk2(sa, sb);

        u64 b1 = 0, b2 = 0, d1 = 0, d2 = 0;
        ulonglong2 f0 = sAB[NHARM];
        ulonglong2 f1 = sAB[NHARM - 1];
        #pragma unroll
        for (int k = NHARM; k >= 1; --k) {
            const u64 Ak = f0.x, Bk = f0.y;
            f0 = f1;
            if (k >= 2) f1 = sAB[k - 2];
            u64 nb;
            nb = fma2(tw, b1, sub2(Ak, b2)); b2 = b1; b1 = nb;
            nb = fma2(tw, d1, sub2(Bk, d2)); d2 = d1; d1 = nb;
        }
        const u64 A0 = f0.x;                 // sAB[0].x via pipeline
        u64 fv = sub2(A0, b2);
        fv = fma2(cu, b1, fv);
        fv = fma2(su, d1, fv);
        float g0, g1;
        upk2(fv, g0, g1);
        reinterpret_cast<float2*>(g)[t] = make_float2(g0, g1);
    }
    __syncthreads();

    // ---- stencil table: t4[j] = (g[j-1], g[j], g[j+1], g[j+2]) ----
    #pragma unroll
    for (int r = 0; r < 2; ++r) {
        const int j = t + r * 1024;
        t4[j] = make_float4(g[(j + TSIZE - 1) & (TSIZE - 1)],
                            g[j],
                            g[(j + 1) & (TSIZE - 1)],
                            g[(j + 2) & (TSIZE - 1)]);
    }
    __syncthreads();

    // ---- evaluation: range-reduce + cubic Lagrange ----
    if (!act) return;

    const float SCALE = 2048.0f / 3.14159265358979323846f;
    float th[4] = {xv.x, xv.y, xv.z, xv.w};
    float res[4];
    #pragma unroll
    for (int e = 0; e < 4; ++e) {
        const float u  = th[e] * SCALE;
        const float fl = floorf(u);
        const float f  = u - fl;
        const int idx  = ((int)fl) & (TSIZE - 1);
        const float4 p = t4[idx];
        const float fm1 = f - 1.0f, fm2 = f - 2.0f, fp1 = f + 1.0f;
        const float w0 = -f * fm1 * fm2 * (1.0f / 6.0f);
        const float w1 =  fp1 * fm1 * fm2 * 0.5f;
        const float w2 = -fp1 * f * fm2 * 0.5f;
        const float w3 =  fp1 * f * fm1 * (1.0f / 6.0f);
        res[e] = fmaf(w0, p.x, fmaf(w1, p.y, fmaf(w2, p.z, w3 * p.w)));
    }

    out4[T] = make_float4(fmaf(av.x, res[0], bb), fmaf(av.y, res[1], bb),
                          fmaf(av.z, res[2], bb), fmaf(av.w, res[3], bb));
}

// ---------------------------------------------------------------------------
// Fallback for unexpected shapes (direct chain evaluation).
// ---------------------------------------------------------------------------
__global__ void __launch_bounds__(256)
qsp_generic(const float* __restrict__ x,
            const float* __restrict__ phis,
            const float* __restrict__ alphas,
            const float* __restrict__ bias,
            float* __restrict__ out,
            int n, int nsteps)
{
    __shared__ float pc[256], ps[256];
    __shared__ float s0c, s0s;
    int t = threadIdx.x;
    if (t < nsteps && t < 256) {
        float sp, cp; sincosf(phis[t + 1], &sp, &cp);
        pc[t] = cp; ps[t] = sp;
    }
    if (t == 0) {
        float sp, cp; sincosf(phis[0], &sp, &cp);
        s0c = cp; s0s = sp;
    }
    __syncthreads();

    const int i = blockIdx.x * blockDim.x + t;
    if (i >= n) return;

    float s, c; sincosf(x[i], &s, &c);
    float x0 = 1.0f, y0 = 0.0f, x1 = 0.0f, y1 = 0.0f;
    for (int k = 0; k < nsteps; ++k) {
        const float ec = (k < 256) ? pc[k] : cosf(phis[k + 1]);
        const float es = (k < 256) ? ps[k] : sinf(phis[k + 1]);
        const float ux = c * x0 - s * y1;
        const float uy = c * y0 + s * x1;
        const float vx = c * x1 - s * y0;
        const float vy = c * y1 + s * x0;
        x0 = ec * ux - es * uy;
        y0 = es * ux + ec * uy;
        x1 = ec * vx + es * vy;
        y1 = ec * vy - es * vx;
    }
    const float re = s0c * x0 - s0s * y0;
    out[i] = fmaf(alphas[i], re, bias[0]);
}

extern "C" void kernel_launch(void* const* d_in, const int* in_sizes, int n_in,
                              void* d_out, int out_size)
{
    const float* x      = (const float*)d_in[0];
    const float* phis   = (const float*)d_in[1];
    const float* alphas = (const float*)d_in[2];
    const float* bias   = (const float*)d_in[3];
    float* out = (float*)d_out;

    const int n      = in_sizes[0];
    const int nph    = in_sizes[1];
    const int nsteps = nph - 1;

    if (nsteps == NSTEP && (n & 3) == 0) {
        const int nq      = n >> 2;                   // float4 quads
        const int threads = 1024;
        const int blocks  = (nq + threads - 1) / threads;   // 128 for n=524288
        qsp_fused<<<blocks, threads>>>((const float4*)x, phis,
                                       (const float4*)alphas, bias,
                                       (float4*)out, nq);
    } else {
        const int threads = 256;
        const int blocks  = (n + threads - 1) / threads;
        qsp_generic<<<blocks, threads>>>(x, phis, alphas, bias, out, n, nsteps);
    }
}